// round 13
// baseline (speedup 1.0000x reference)
#include <cuda_runtime.h>
#include <cuda_bf16.h>
#include <cstdint>

#define DM   1024
#define NH   16
#define DKH  64
#define NB   4
#define SQ   2048
#define MTOT (NB*SQ)   // 8192

// ---------------- scratch (device globals; no allocs allowed) ----------------
__device__ __nv_bfloat16 g_whi[4][DM*DM];     // wq, wk, wv, wo (bf16 hi)
__device__ __nv_bfloat16 g_wlo[4][DM*DM];     // bf16 lo
__device__ __nv_bfloat16 g_phi[3][MTOT*DM];   // projected q,k,v (head-split, hi)
__device__ __nv_bfloat16 g_plo[3][MTOT*DM];   // projected q,k,v (head-split, lo)
__device__ float g_ao[MTOT*DM];               // attention output, fp32 [B,S,1024]

// ---------------- helpers ----------------
__device__ __forceinline__ uint32_t smem_u32(const void* p) {
    uint32_t a;
    asm("{ .reg .u64 t; cvta.to.shared.u64 t, %1; cvt.u32.u64 %0, t; }" : "=r"(a) : "l"(p));
    return a;
}
__device__ __forceinline__ void ldsm4(uint32_t* r, uint32_t addr) {
    asm volatile("ldmatrix.sync.aligned.m8n8.x4.shared.b16 {%0,%1,%2,%3}, [%4];"
                 : "=r"(r[0]), "=r"(r[1]), "=r"(r[2]), "=r"(r[3]) : "r"(addr));
}
__device__ __forceinline__ void ldsm4t(uint32_t* r, uint32_t addr) {
    asm volatile("ldmatrix.sync.aligned.m8n8.x4.trans.shared.b16 {%0,%1,%2,%3}, [%4];"
                 : "=r"(r[0]), "=r"(r[1]), "=r"(r[2]), "=r"(r[3]) : "r"(addr));
}
__device__ __forceinline__ void mma_bf16(float* d, const uint32_t* a, const uint32_t* b) {
    asm volatile("mma.sync.aligned.m16n8k16.row.col.f32.bf16.bf16.f32 "
                 "{%0,%1,%2,%3}, {%4,%5,%6,%7}, {%8,%9}, {%0,%1,%2,%3};"
                 : "+f"(d[0]), "+f"(d[1]), "+f"(d[2]), "+f"(d[3])
                 : "r"(a[0]), "r"(a[1]), "r"(a[2]), "r"(a[3]), "r"(b[0]), "r"(b[1]));
}
__device__ __forceinline__ float ex2(float x) {
    float y; asm("ex2.approx.ftz.f32 %0, %1;" : "=f"(y) : "f"(x)); return y;
}
#define CP_ASYNC16(dst, src) \
    asm volatile("cp.async.cg.shared.global [%0], [%1], 16;" :: "r"(dst), "l"(src))
#define CP_COMMIT() asm volatile("cp.async.commit_group;" ::: "memory")
#define CP_WAIT(N)  asm volatile("cp.async.wait_group %0;" :: "n"(N) : "memory")

__device__ __forceinline__ uint32_t bf2_bits(__nv_bfloat162 v) {
    uint32_t u; __builtin_memcpy(&u, &v, 4); return u;
}
__device__ __forceinline__ void split2(float x, float y, uint32_t& hi, uint32_t& lo) {
    __nv_bfloat162 H = __floats2bfloat162_rn(x, y);
    __nv_bfloat162 L = __floats2bfloat162_rn(x - __bfloat162float(H.x),
                                             y - __bfloat162float(H.y));
    hi = bf2_bits(H); lo = bf2_bits(L);
}

// ============================================================
// Weight split (inputs are consumed fp32 by the GEMM)
// ============================================================
__global__ __launch_bounds__(256)
void split_w4(const float* __restrict__ w0, const float* __restrict__ w1,
              const float* __restrict__ w2, const float* __restrict__ w3)
{
    int i = blockIdx.x * blockDim.x + threadIdx.x;
    int s = blockIdx.y;
    const float* w = (s == 0) ? w0 : (s == 1) ? w1 : (s == 2) ? w2 : w3;
    float4 v = ((const float4*)w)[i];
    uint32_t h0, l0, h1, l1;
    split2(v.x, v.y, h0, l0);
    split2(v.z, v.w, h1, l1);
    uint32_t* hp = (uint32_t*)g_whi[s];
    uint32_t* lp = (uint32_t*)g_wlo[s];
    hp[i*2] = h0; hp[i*2+1] = h1;
    lp[i*2] = l0; lp[i*2+1] = l1;
}

// ============================================================
// HMMA GEMM: BK=64 (16 chunks -> half the barriers), fp32 A staged
// in two ldg/sts half-phases interleaved with compute, B bf16 hi/lo
// via 2-stage cp.async. CTA 128x64, 8 warps (32x32), 2 CTAs/SM.
// mode 1 (grid.z 0..2): x[z] @ W[z]^T -> g_phi/g_plo[z] head-split
// mode 0: g_ao @ W[3]^T + bias -> fp32 outF row-major
// ============================================================
#define GBM 128
#define GBN 64
#define GBK 64
#define NCHUNK (DM/GBK)    // 16
#define A_HI 0             // per A buffer: hi 128x128B, lo 128x128B
#define A_LO 16384
#define ABUFSZ 32768       // 2 buffers
#define B_OFF 65536        // per B stage: hi 64x128B, lo 64x128B = 16KB
#define B_HI 0
#define B_LO 8192
#define BBUFSZ 16384       // 2 stages
#define GEMM_SMEM 98304

// load one half of next A chunk: rows [h*64, h*64+64), 4 float4/thread
__device__ __forceinline__ void ldgA_half(const float* __restrict__ A, int m0, int kb,
                                          int half, int tid, float4* areg)
{
#pragma unroll
    for (int i = 0; i < 4; i++) {
        int e = tid + (i << 8) + (half << 10);   // 0..2047
        int row = e >> 4, f4 = e & 15;           // 16 float4 per 64-float row
        areg[i] = __ldg((const float4*)(A + (size_t)(m0 + row) * DM + kb) + f4);
    }
}

__device__ __forceinline__ void stsA_half(uint32_t abuf, int half, int tid,
                                          const float4* areg)
{
#pragma unroll
    for (int i = 0; i < 4; i++) {
        int e = tid + (i << 8) + (half << 10);
        int row = e >> 4, f4 = e & 15;
        int un = f4 >> 1;
        uint32_t hb = (uint32_t)(f4 & 1) << 3;
        uint32_t rs = (uint32_t)row << 7;
        uint32_t sw = rs | ((uint32_t)((un ^ (row & 7)) & 7) << 4) | hb;
        float4 v = areg[i];
        uint32_t h0, l0, h1, l1;
        split2(v.x, v.y, h0, l0);
        split2(v.z, v.w, h1, l1);
        asm volatile("st.shared.v2.b32 [%0], {%1,%2};" :: "r"(abuf + A_HI + sw), "r"(h0), "r"(h1));
        asm volatile("st.shared.v2.b32 [%0], {%1,%2};" :: "r"(abuf + A_LO + sw), "r"(l0), "r"(l1));
    }
}

__device__ __forceinline__ void issueB(uint32_t bbuf,
    const __nv_bfloat16* __restrict__ Bhi, const __nv_bfloat16* __restrict__ Blo,
    int n0, int kb, int tid)
{
#pragma unroll
    for (int i = 0; i < 2; i++) {
        int e = tid + (i << 8);      // 512 units: 64 rows x 8 units
        int row = e >> 3, un = e & 7;
        uint32_t off = ((uint32_t)row << 7) | ((uint32_t)((un ^ (row & 7)) & 7) << 4);
        size_t go = (size_t)(n0 + row) * DM + kb + un * 8;
        CP_ASYNC16(bbuf + B_HI + off, (const char*)(Bhi + go));
        CP_ASYNC16(bbuf + B_LO + off, (const char*)(Blo + go));
    }
}

// one k16-step of the 3-product MMA block
__device__ __forceinline__ void gemm_ks(float acc[2][4][4], uint32_t abuf, uint32_t bbuf,
                                        int ks, int warp_m, int warp_n, int g, int r)
{
    uint32_t Ah[2][4], Al[2][4], Bh[4][2], Bl[4][2];
    {
        int kun = (ks << 1) + (g >> 1);
#pragma unroll
        for (int mi = 0; mi < 2; mi++) {
            int rowl = warp_m + ((g & 1) << 3) + r + (mi << 4);
            uint32_t base = (uint32_t)rowl << 7;
            uint32_t sw = ((uint32_t)((kun ^ (rowl & 7)) & 7) << 4);
            ldsm4(Ah[mi], abuf + A_HI + base + sw);
            ldsm4(Al[mi], abuf + A_LO + base + sw);
        }
    }
    {
        int kun = (ks << 1) + (g & 1);
#pragma unroll
        for (int nh = 0; nh < 2; nh++) {
            int rowl = warp_n + ((g >> 1) << 3) + r + (nh << 4);
            uint32_t base = (uint32_t)rowl << 7;
            uint32_t sw = ((uint32_t)((kun ^ (rowl & 7)) & 7) << 4);
            uint32_t t[4];
            ldsm4(t, bbuf + B_HI + base + sw);
            Bh[nh*2][0] = t[0]; Bh[nh*2][1] = t[1];
            Bh[nh*2+1][0] = t[2]; Bh[nh*2+1][1] = t[3];
            ldsm4(t, bbuf + B_LO + base + sw);
            Bl[nh*2][0] = t[0]; Bl[nh*2][1] = t[1];
            Bl[nh*2+1][0] = t[2]; Bl[nh*2+1][1] = t[3];
        }
    }
#pragma unroll
    for (int mi = 0; mi < 2; mi++)
#pragma unroll
        for (int ni = 0; ni < 4; ni++)
            mma_bf16(acc[mi][ni], Ah[mi], Bh[ni]);
#pragma unroll
    for (int mi = 0; mi < 2; mi++)
#pragma unroll
        for (int ni = 0; ni < 4; ni++)
            mma_bf16(acc[mi][ni], Ah[mi], Bl[ni]);
#pragma unroll
    for (int mi = 0; mi < 2; mi++)
#pragma unroll
        for (int ni = 0; ni < 4; ni++)
            mma_bf16(acc[mi][ni], Al[mi], Bh[ni]);
}

__global__ __launch_bounds__(256, 2)
void gemm_mma(const float* __restrict__ x0, const float* __restrict__ x1,
              const float* __restrict__ x2,
              const float* __restrict__ b0, const float* __restrict__ b1,
              const float* __restrict__ b2, const float* __restrict__ b3,
              float* __restrict__ outF, float qscale, int mode)
{
    extern __shared__ __align__(1024) char smem[];
    const int tid = threadIdx.x;
    const int lane = tid & 31, wid = tid >> 5;
    const int warp_m = (wid & 3) << 5;
    const int warp_n = (wid >> 2) << 5;
    const int m0 = blockIdx.y * GBM;
    const int n0 = blockIdx.x * GBN;
    const int z  = blockIdx.z;
    const uint32_t sbase = smem_u32(smem);

    const float* A = (mode == 0) ? g_ao : (z == 0 ? x0 : (z == 1 ? x1 : x2));
    const int zw = (mode == 0) ? 3 : z;
    const __nv_bfloat16* Bhi = g_whi[zw];
    const __nv_bfloat16* Blo = g_wlo[zw];
    const float* bias = (mode == 0) ? b3 : (z == 0 ? b0 : (z == 1 ? b1 : b2));
    const float scale = (mode == 1 && z == 0) ? qscale : 1.0f;

    float acc[2][4][4];
#pragma unroll
    for (int mi = 0; mi < 2; mi++)
#pragma unroll
        for (int ni = 0; ni < 4; ni++)
#pragma unroll
            for (int q = 0; q < 4; q++) acc[mi][ni][q] = 0.0f;

    const int g = lane >> 3, r = lane & 7;

    // prologue: B0 in flight; A0 staged (halves sequential, regs reused)
    issueB(sbase + B_OFF, Bhi, Blo, n0, 0, tid);
    CP_COMMIT();
    {
        float4 areg[4];
        ldgA_half(A, m0, 0, 0, tid, areg);
        stsA_half(sbase, 0, tid, areg);
        ldgA_half(A, m0, 0, 1, tid, areg);
        stsA_half(sbase, 1, tid, areg);
    }

    for (int kc = 0; kc < NCHUNK; kc++) {
        const uint32_t abuf = sbase + (uint32_t)(kc & 1) * ABUFSZ;
        const uint32_t bbuf = sbase + B_OFF + (uint32_t)(kc & 1) * BBUFSZ;
        const uint32_t abuf_n = sbase + (uint32_t)((kc + 1) & 1) * ABUFSZ;
        CP_WAIT(0);          // B(kc) landed
        __syncthreads();     // prev chunk's reads done; A(kc) STS visible
        const bool more = (kc + 1 < NCHUNK);
        if (more) {
            issueB(sbase + B_OFF + (uint32_t)((kc + 1) & 1) * BBUFSZ,
                   Bhi, Blo, n0, (kc + 1) * GBK, tid);
            CP_COMMIT();
        }

        float4 areg[4];
        if (more) ldgA_half(A, m0, (kc + 1) * GBK, 0, tid, areg);

        gemm_ks(acc, abuf, bbuf, 0, warp_m, warp_n, g, r);
        gemm_ks(acc, abuf, bbuf, 1, warp_m, warp_n, g, r);

        if (more) {
            stsA_half(abuf_n, 0, tid, areg);
            ldgA_half(A, m0, (kc + 1) * GBK, 1, tid, areg);
        }

        gemm_ks(acc, abuf, bbuf, 2, warp_m, warp_n, g, r);
        gemm_ks(acc, abuf, bbuf, 3, warp_m, warp_n, g, r);

        if (more) stsA_half(abuf_n, 1, tid, areg);
    }

    __nv_bfloat16* outHi = g_phi[z];
    __nv_bfloat16* outLo = g_plo[z];
    const int er = lane >> 2, ec = (lane & 3) << 1;
#pragma unroll
    for (int mi = 0; mi < 2; mi++) {
#pragma unroll
        for (int ni = 0; ni < 4; ni++) {
            int col = n0 + warp_n + (ni << 3) + ec;
            float bx = __ldg(bias + col), by = __ldg(bias + col + 1);
#pragma unroll
            for (int half = 0; half < 2; half++) {
                int row = m0 + warp_m + (mi << 4) + er + (half << 3);
                float ox = (acc[mi][ni][half*2+0] + bx) * scale;
                float oy = (acc[mi][ni][half*2+1] + by) * scale;
                if (mode == 0) {
                    float2 o; o.x = ox; o.y = oy;
                    *(float2*)(outF + (size_t)row * DM + col) = o;
                } else {
                    int b = row >> 11, s = row & 2047;
                    int h = col >> 6, dk = col & 63;
                    size_t idx = ((size_t)(b * NH + h) * SQ + s) * DKH + dk;
                    uint32_t hi, lo;
                    split2(ox, oy, hi, lo);
                    *(uint32_t*)(outHi + idx) = hi;
                    *(uint32_t*)(outLo + idx) = lo;
                }
            }
        }
    }
}

// ============================================================
// Flash attention on HMMA (unchanged from R12 — passing config):
// bf16 3-product, Q re-ldmatrix'd per tile, 2-stage KV, 2 CTAs/SM,
// raw ex2 softmax, deferred l-reduce, fp32 AO out.
// ============================================================
#define AQ_HI 0
#define AQ_LO 16384
#define AKV   32768
#define KVSZ  32768
#define AK_HI 0
#define AK_LO 8192
#define AV_HI 16384
#define AV_LO 24576
#define ATTN_SMEM (32768 + 2*KVSZ)   // 98304

__device__ __forceinline__ void issue_kv(uint32_t dst,
    const __nv_bfloat16* __restrict__ Kh, const __nv_bfloat16* __restrict__ Kl,
    const __nv_bfloat16* __restrict__ Vh, const __nv_bfloat16* __restrict__ Vl,
    int tid)
{
#pragma unroll
    for (int i = 0; i < 2; i++) {
        int e = tid + (i << 8);
        int row = e >> 3, un = e & 7;
        uint32_t off = ((uint32_t)row << 7) | ((uint32_t)((un ^ (row & 7)) & 7) << 4);
        size_t go = (size_t)row * DKH + un * 8;
        CP_ASYNC16(dst + AK_HI + off, (const char*)(Kh + go));
        CP_ASYNC16(dst + AK_LO + off, (const char*)(Kl + go));
        CP_ASYNC16(dst + AV_HI + off, (const char*)(Vh + go));
        CP_ASYNC16(dst + AV_LO + off, (const char*)(Vl + go));
    }
}

__global__ __launch_bounds__(256, 2)
void attn_mma()
{
    extern __shared__ __align__(1024) char smem[];
    const int tid = threadIdx.x, lane = tid & 31, wid = tid >> 5;
    const int g = lane >> 3, r = lane & 7;
    const int bq = blockIdx.x << 7, h = blockIdx.y, b = blockIdx.z;
    const size_t ho = (size_t)(b * NH + h) * SQ * DKH;
    const __nv_bfloat16* Qh = g_phi[0] + ho + (size_t)bq * DKH;
    const __nv_bfloat16* Ql = g_plo[0] + ho + (size_t)bq * DKH;
    const __nv_bfloat16* Kh = g_phi[1] + ho;
    const __nv_bfloat16* Kl = g_plo[1] + ho;
    const __nv_bfloat16* Vh = g_phi[2] + ho;
    const __nv_bfloat16* Vl = g_plo[2] + ho;
    const uint32_t sb = smem_u32(smem);

#pragma unroll
    for (int i = 0; i < 4; i++) {
        int e = tid + (i << 8);
        int row = e >> 3, un = e & 7;
        uint32_t off = ((uint32_t)row << 7) | ((uint32_t)((un ^ (row & 7)) & 7) << 4);
        size_t go = (size_t)row * DKH + un * 8;
        CP_ASYNC16(sb + AQ_HI + off, (const char*)(Qh + go));
        CP_ASYNC16(sb + AQ_LO + off, (const char*)(Ql + go));
    }
    issue_kv(sb + AKV, Kh, Kl, Vh, Vl, tid);
    CP_COMMIT();

    float O[8][4];
#pragma unroll
    for (int nf = 0; nf < 8; nf++)
#pragma unroll
        for (int q = 0; q < 4; q++) O[nf][q] = 0.0f;
    float lsum[2] = {0.0f, 0.0f};

    const int qrow = (wid << 4) + ((g & 1) << 3) + r;
    const uint32_t qbase = (uint32_t)qrow << 7;

    const int NT = SQ / 64;  // 32
    for (int t = 0; t < NT; t++) {
        const uint32_t buf = sb + AKV + (uint32_t)(t & 1) * KVSZ;
        CP_WAIT(0);
        __syncthreads();
        if (t + 1 < NT) {
            size_t jo = (size_t)(t + 1) * 64 * DKH;
            issue_kv(sb + AKV + (uint32_t)((t + 1) & 1) * KVSZ,
                     Kh + jo, Kl + jo, Vh + jo, Vl + jo, tid);
        }
        CP_COMMIT();

        // ---- S = Q K^T ----
        float S[8][4];
#pragma unroll
        for (int nf = 0; nf < 8; nf++)
#pragma unroll
            for (int q = 0; q < 4; q++) S[nf][q] = 0.0f;

#pragma unroll
        for (int ks = 0; ks < 4; ks++) {
            uint32_t Qfh[4], Qfl[4];
            {
                int un = (ks << 1) + (g >> 1);
                uint32_t off = qbase | ((uint32_t)((un ^ (qrow & 7)) & 7) << 4);
                ldsm4(Qfh, sb + AQ_HI + off);
                ldsm4(Qfl, sb + AQ_LO + off);
            }
            uint32_t Bh[8][2], Bl[8][2];
#pragma unroll
            for (int pp = 0; pp < 4; pp++) {
                int row = (pp << 4) + ((g >> 1) << 3) + r;
                int un = (ks << 1) + (g & 1);
                uint32_t off = ((uint32_t)row << 7) | ((uint32_t)((un ^ (row & 7)) & 7) << 4);
                uint32_t tt[4];
                ldsm4(tt, buf + AK_HI + off);
                Bh[pp*2][0] = tt[0]; Bh[pp*2][1] = tt[1];
                Bh[pp*2+1][0] = tt[2]; Bh[pp*2+1][1] = tt[3];
                ldsm4(tt, buf + AK_LO + off);
                Bl[pp*2][0] = tt[0]; Bl[pp*2][1] = tt[1];
                Bl[pp*2+1][0] = tt[2]; Bl[pp*2+1][1] = tt[3];
            }
#pragma unroll
            for (int nf = 0; nf < 8; nf++)
                mma_bf16(S[nf], Qfh, Bh[nf]);
#pragma unroll
            for (int nf = 0; nf < 8; nf++)
                mma_bf16(S[nf], Qfh, Bl[nf]);
#pragma unroll
            for (int nf = 0; nf < 8; nf++)
                mma_bf16(S[nf], Qfl, Bh[nf]);
        }

        // ---- softmax: p = 2^S (log2e folded into Q scale) ----
#pragma unroll
        for (int hh = 0; hh < 2; hh++) {
            float sum = 0.0f;
#pragma unroll
            for (int nf = 0; nf < 8; nf++) {
                float p0 = ex2(S[nf][hh*2]);
                float p1 = ex2(S[nf][hh*2+1]);
                S[nf][hh*2] = p0; S[nf][hh*2+1] = p1;
                sum += p0 + p1;
            }
            lsum[hh] += sum;
        }

        // ---- O += P V ----
#pragma unroll
        for (int js = 0; js < 4; js++) {
            uint32_t Ph[4], Pl[4];
            split2(S[js*2][0],   S[js*2][1],   Ph[0], Pl[0]);
            split2(S[js*2][2],   S[js*2][3],   Ph[1], Pl[1]);
            split2(S[js*2+1][0], S[js*2+1][1], Ph[2], Pl[2]);
            split2(S[js*2+1][2], S[js*2+1][3], Ph[3], Pl[3]);

            uint32_t Vbh[8][2], Vbl[8][2];
#pragma unroll
            for (int pp = 0; pp < 4; pp++) {
                int row = (js << 4) + ((g & 1) << 3) + r;
                int un = (pp << 1) + (g >> 1);
                uint32_t off = ((uint32_t)row << 7) | ((uint32_t)((un ^ (row & 7)) & 7) << 4);
                uint32_t tt[4];
                ldsm4t(tt, buf + AV_HI + off);
                Vbh[pp*2][0] = tt[0]; Vbh[pp*2][1] = tt[1];
                Vbh[pp*2+1][0] = tt[2]; Vbh[pp*2+1][1] = tt[3];
                ldsm4t(tt, buf + AV_LO + off);
                Vbl[pp*2][0] = tt[0]; Vbl[pp*2][1] = tt[1];
                Vbl[pp*2+1][0] = tt[2]; Vbl[pp*2+1][1] = tt[3];
            }
#pragma unroll
            for (int nf = 0; nf < 8; nf++)
                mma_bf16(O[nf], Ph, Vbh[nf]);
#pragma unroll
            for (int nf = 0; nf < 8; nf++)
                mma_bf16(O[nf], Ph, Vbl[nf]);
#pragma unroll
            for (int nf = 0; nf < 8; nf++)
                mma_bf16(O[nf], Pl, Vbh[nf]);
        }
    }

    // ---- epilogue ----
#pragma unroll
    for (int hh = 0; hh < 2; hh++) {
        lsum[hh] += __shfl_xor_sync(0xffffffffu, lsum[hh], 1);
        lsum[hh] += __shfl_xor_sync(0xffffffffu, lsum[hh], 2);
    }
    float inv0 = 1.0f / lsum[0], inv1 = 1.0f / lsum[1];
    int q0 = bq + (wid << 4) + (lane >> 2);
    size_t base0 = ((size_t)(b * SQ + q0)) * DM + h * DKH;
    size_t base1 = base0 + (size_t)8 * DM;
#pragma unroll
    for (int nf = 0; nf < 8; nf++) {
        int dk = (nf << 3) + ((lane & 3) << 1);
        float2 o0; o0.x = O[nf][0] * inv0; o0.y = O[nf][1] * inv0;
        *(float2*)(g_ao + base0 + dk) = o0;
        float2 o1; o1.x = O[nf][2] * inv1; o1.y = O[nf][3] * inv1;
        *(float2*)(g_ao + base1 + dk) = o1;
    }
}

// ============================================================
extern "C" void kernel_launch(void* const* d_in, const int* in_sizes, int n_in,
                              void* d_out, int out_size)
{
    (void)in_sizes; (void)n_in; (void)out_size;
    const float* query = (const float*)d_in[0];
    const float* key   = (const float*)d_in[1];
    const float* value = (const float*)d_in[2];
    const float* w_q = (const float*)d_in[3];
    const float* b_q = (const float*)d_in[4];
    const float* w_k = (const float*)d_in[5];
    const float* b_k = (const float*)d_in[6];
    const float* w_v = (const float*)d_in[7];
    const float* b_v = (const float*)d_in[8];
    const float* w_o = (const float*)d_in[9];
    const float* b_o = (const float*)d_in[10];
    float* out = (float*)d_out;

    cudaFuncSetAttribute(gemm_mma, cudaFuncAttributeMaxDynamicSharedMemorySize, GEMM_SMEM);
    cudaFuncSetAttribute(attn_mma, cudaFuncAttributeMaxDynamicSharedMemorySize, ATTN_SMEM);

    dim3 cw(DM * DM / 4 / 256, 4);         // weight splits
    dim3 gqkv(DM / GBN, MTOT / GBM, 3);    // (16, 64, 3)
    dim3 gout(DM / GBN, MTOT / GBM, 1);    // (16, 64, 1)
    dim3 agrid(SQ / 128, NH, NB);          // (16, 16, 4)

    const float qscale = 0.125f * 1.44269504088896340736f;  // 1/sqrt(dk) * log2(e)

    split_w4<<<cw, 256>>>(w_q, w_k, w_v, w_o);
    gemm_mma<<<gqkv, 256, GEMM_SMEM>>>(query, key, value,
                                       b_q, b_k, b_v, b_o, nullptr, qscale, 1);
    attn_mma<<<agrid, 256, ATTN_SMEM>>>();
    gemm_mma<<<gout, 256, GEMM_SMEM>>>(query, key, value,
                                       b_q, b_k, b_v, b_o, out, qscale, 0);
}

// round 14
// speedup vs baseline: 1.5319x; 1.5319x over previous
#include <cuda_runtime.h>
#include <cuda_bf16.h>
#include <cstdint>

#define DM   1024
#define NH   16
#define DKH  64
#define NB   4
#define SQ   2048
#define MTOT (NB*SQ)   // 8192

// ---------------- scratch (device globals; no allocs allowed) ----------------
__device__ __nv_bfloat16 g_xhi[3][MTOT*DM];   // input splits (q,k,v); [0] reused for AO
__device__ __nv_bfloat16 g_xlo[3][MTOT*DM];
__device__ __nv_bfloat16 g_whi[4][DM*DM];     // wq, wk, wv, wo
__device__ __nv_bfloat16 g_wlo[4][DM*DM];
__device__ __nv_bfloat16 g_phi[3][MTOT*DM];   // projected q,k,v (head-split, hi)
__device__ __nv_bfloat16 g_plo[3][MTOT*DM];   // projected q,k,v (head-split, lo)

// ---------------- helpers ----------------
__device__ __forceinline__ uint32_t smem_u32(const void* p) {
    uint32_t a;
    asm("{ .reg .u64 t; cvta.to.shared.u64 t, %1; cvt.u32.u64 %0, t; }" : "=r"(a) : "l"(p));
    return a;
}
__device__ __forceinline__ void ldsm4(uint32_t* r, uint32_t addr) {
    asm volatile("ldmatrix.sync.aligned.m8n8.x4.shared.b16 {%0,%1,%2,%3}, [%4];"
                 : "=r"(r[0]), "=r"(r[1]), "=r"(r[2]), "=r"(r[3]) : "r"(addr));
}
__device__ __forceinline__ void ldsm4t(uint32_t* r, uint32_t addr) {
    asm volatile("ldmatrix.sync.aligned.m8n8.x4.trans.shared.b16 {%0,%1,%2,%3}, [%4];"
                 : "=r"(r[0]), "=r"(r[1]), "=r"(r[2]), "=r"(r[3]) : "r"(addr));
}
__device__ __forceinline__ void mma_bf16(float* d, const uint32_t* a, const uint32_t* b) {
    asm volatile("mma.sync.aligned.m16n8k16.row.col.f32.bf16.bf16.f32 "
                 "{%0,%1,%2,%3}, {%4,%5,%6,%7}, {%8,%9}, {%0,%1,%2,%3};"
                 : "+f"(d[0]), "+f"(d[1]), "+f"(d[2]), "+f"(d[3])
                 : "r"(a[0]), "r"(a[1]), "r"(a[2]), "r"(a[3]), "r"(b[0]), "r"(b[1]));
}
__device__ __forceinline__ float ex2(float x) {
    float y; asm("ex2.approx.ftz.f32 %0, %1;" : "=f"(y) : "f"(x)); return y;
}
#define CP_ASYNC16(dst, src) \
    asm volatile("cp.async.cg.shared.global [%0], [%1], 16;" :: "r"(dst), "l"(src))
#define CP_COMMIT() asm volatile("cp.async.commit_group;" ::: "memory")
#define CP_WAIT(N)  asm volatile("cp.async.wait_group %0;" :: "n"(N) : "memory")

__device__ __forceinline__ uint32_t bf2_bits(__nv_bfloat162 v) {
    uint32_t u; __builtin_memcpy(&u, &v, 4); return u;
}
__device__ __forceinline__ void split2(float x, float y, uint32_t& hi, uint32_t& lo) {
    __nv_bfloat162 H = __floats2bfloat162_rn(x, y);
    __nv_bfloat162 L = __floats2bfloat162_rn(x - __bfloat162float(H.x),
                                             y - __bfloat162float(H.y));
    hi = bf2_bits(H); lo = bf2_bits(L);
}

// ============================================================
// One split launch: y=0..2 inputs, y=3..6 weights
// ============================================================
__global__ __launch_bounds__(256)
void split_all(const float* __restrict__ x0, const float* __restrict__ x1,
               const float* __restrict__ x2, const float* __restrict__ w0,
               const float* __restrict__ w1, const float* __restrict__ w2,
               const float* __restrict__ w3)
{
    int i = blockIdx.x * blockDim.x + threadIdx.x;
    int s = blockIdx.y;
    const float* src;
    uint32_t *hp, *lp;
    if (s < 3) {
        src = (s == 0) ? x0 : (s == 1) ? x1 : x2;
        hp = (uint32_t*)g_xhi[s]; lp = (uint32_t*)g_xlo[s];
    } else {
        if (i >= DM * DM / 4) return;
        int w = s - 3;
        src = (w == 0) ? w0 : (w == 1) ? w1 : (w == 2) ? w2 : w3;
        hp = (uint32_t*)g_whi[w]; lp = (uint32_t*)g_wlo[w];
    }
    float4 v = ((const float4*)src)[i];
    uint32_t h0, l0, h1, l1;
    split2(v.x, v.y, h0, l0);
    split2(v.z, v.w, h1, l1);
    hp[i*2] = h0; hp[i*2+1] = h1;
    lp[i*2] = l0; lp[i*2+1] = l1;
}

// ============================================================
// HMMA GEMM: CTA tile 128x64, BK=32, hi|lo packed 128B rows,
// 3-stage cp.async, 8 warps (warp tile 32x32), 2 CTAs/SM.
// mode 1 (grid.z 0..2): g_xhi[z] @ g_whi[z]^T -> g_phi[z] head-split
// mode 0: g_xhi[0] @ g_whi[3]^T -> fp32 outF row-major
// ============================================================
#define GBM 128
#define GBN 64
#define GBK 32
#define NCHUNK (DM/GBK)    // 32
#define GA_OFF 0
#define GB_OFF 16384
#define BUFSZ  24576
#define GEMM_SMEM (3*BUFSZ)   // 73728

__device__ __forceinline__ void issue_chunk(uint32_t sbuf,
    const __nv_bfloat16* __restrict__ Ahi, const __nv_bfloat16* __restrict__ Alo,
    const __nv_bfloat16* __restrict__ Bhi, const __nv_bfloat16* __restrict__ Blo,
    int m0, int n0, int kb, int tid)
{
#pragma unroll
    for (int i = 0; i < 6; i++) {
        int e = tid + (i << 8);
        if (e < 1024) {
            int row = e >> 3, un = e & 7;
            uint32_t off = ((uint32_t)row << 7) | ((uint32_t)((un ^ (row & 7)) & 7) << 4);
            const __nv_bfloat16* src = (un < 4 ? Ahi : Alo)
                                     + (size_t)(m0 + row) * DM + kb + (un & 3) * 8;
            CP_ASYNC16(sbuf + GA_OFF + off, (const char*)src);
        } else {
            int eb = e - 1024;
            int row = eb >> 3, un = eb & 7;
            uint32_t off = ((uint32_t)row << 7) | ((uint32_t)((un ^ (row & 7)) & 7) << 4);
            const __nv_bfloat16* src = (un < 4 ? Bhi : Blo)
                                     + (size_t)(n0 + row) * DM + kb + (un & 3) * 8;
            CP_ASYNC16(sbuf + GB_OFF + off, (const char*)src);
        }
    }
}

__global__ __launch_bounds__(256, 2)
void gemm_mma(const float* __restrict__ b0, const float* __restrict__ b1,
              const float* __restrict__ b2, const float* __restrict__ b3,
              float* __restrict__ outF, float qscale, int mode)
{
    extern __shared__ __align__(1024) char smem[];
    const int tid = threadIdx.x;
    const int lane = tid & 31, wid = tid >> 5;
    const int warp_m = (wid & 3) << 5;    // 0,32,64,96
    const int warp_n = (wid >> 2) << 5;   // 0,32
    const int m0 = blockIdx.y * GBM;
    const int n0 = blockIdx.x * GBN;
    const int z  = blockIdx.z;
    const uint32_t sbase = smem_u32(smem);

    const int za = (mode == 0) ? 0 : z;
    const int zw = (mode == 0) ? 3 : z;
    const __nv_bfloat16* Ahi = g_xhi[za];
    const __nv_bfloat16* Alo = g_xlo[za];
    const __nv_bfloat16* Bhi = g_whi[zw];
    const __nv_bfloat16* Blo = g_wlo[zw];
    const float* bias = (mode == 0) ? b3 : (z == 0 ? b0 : (z == 1 ? b1 : b2));
    const float scale = (mode == 1 && z == 0) ? qscale : 1.0f;

    float acc[2][4][4];
#pragma unroll
    for (int mi = 0; mi < 2; mi++)
#pragma unroll
        for (int ni = 0; ni < 4; ni++)
#pragma unroll
            for (int q = 0; q < 4; q++) acc[mi][ni][q] = 0.0f;

    const int g = lane >> 3, r = lane & 7;

    issue_chunk(sbase, Ahi, Alo, Bhi, Blo, m0, n0, 0, tid);
    CP_COMMIT();
    issue_chunk(sbase + BUFSZ, Ahi, Alo, Bhi, Blo, m0, n0, GBK, tid);
    CP_COMMIT();

    for (int kc = 0; kc < NCHUNK; kc++) {
        const uint32_t buf = sbase + (uint32_t)(kc % 3) * BUFSZ;
        CP_WAIT(1);
        __syncthreads();
        if (kc + 2 < NCHUNK)
            issue_chunk(sbase + (uint32_t)((kc + 2) % 3) * BUFSZ,
                        Ahi, Alo, Bhi, Blo, m0, n0, (kc + 2) * GBK, tid);
        CP_COMMIT();

#pragma unroll
        for (int ks = 0; ks < 2; ks++) {
            uint32_t Ah[2][4], Al[2][4], Bh[4][2], Bl[4][2];
            {
                int kun = (ks << 1) + (g >> 1);
#pragma unroll
                for (int mi = 0; mi < 2; mi++) {
                    int rowl = warp_m + ((g & 1) << 3) + r + (mi << 4);
                    uint32_t base = (uint32_t)rowl << 7;
                    ldsm4(Ah[mi], buf + GA_OFF + base + ((uint32_t)((kun ^ (rowl & 7)) & 7) << 4));
                    ldsm4(Al[mi], buf + GA_OFF + base + ((uint32_t)(((kun + 4) ^ (rowl & 7)) & 7) << 4));
                }
            }
            {
                int kun = (ks << 1) + (g & 1);
#pragma unroll
                for (int nh = 0; nh < 2; nh++) {
                    int rowl = warp_n + ((g >> 1) << 3) + r + (nh << 4);
                    uint32_t base = (uint32_t)rowl << 7;
                    uint32_t t[4];
                    ldsm4(t, buf + GB_OFF + base + ((uint32_t)((kun ^ (rowl & 7)) & 7) << 4));
                    Bh[nh*2][0] = t[0]; Bh[nh*2][1] = t[1];
                    Bh[nh*2+1][0] = t[2]; Bh[nh*2+1][1] = t[3];
                    ldsm4(t, buf + GB_OFF + base + ((uint32_t)(((kun + 4) ^ (rowl & 7)) & 7) << 4));
                    Bl[nh*2][0] = t[0]; Bl[nh*2][1] = t[1];
                    Bl[nh*2+1][0] = t[2]; Bl[nh*2+1][1] = t[3];
                }
            }
#pragma unroll
            for (int mi = 0; mi < 2; mi++)
#pragma unroll
                for (int ni = 0; ni < 4; ni++)
                    mma_bf16(acc[mi][ni], Ah[mi], Bh[ni]);
#pragma unroll
            for (int mi = 0; mi < 2; mi++)
#pragma unroll
                for (int ni = 0; ni < 4; ni++)
                    mma_bf16(acc[mi][ni], Ah[mi], Bl[ni]);
#pragma unroll
            for (int mi = 0; mi < 2; mi++)
#pragma unroll
                for (int ni = 0; ni < 4; ni++)
                    mma_bf16(acc[mi][ni], Al[mi], Bh[ni]);
        }
    }

    __nv_bfloat16* outHi = g_phi[z];
    __nv_bfloat16* outLo = g_plo[z];
    const int er = lane >> 2, ec = (lane & 3) << 1;
#pragma unroll
    for (int mi = 0; mi < 2; mi++) {
#pragma unroll
        for (int ni = 0; ni < 4; ni++) {
            int col = n0 + warp_n + (ni << 3) + ec;
            float bx = __ldg(bias + col), by = __ldg(bias + col + 1);
#pragma unroll
            for (int half = 0; half < 2; half++) {
                int row = m0 + warp_m + (mi << 4) + er + (half << 3);
                float ox = (acc[mi][ni][half*2+0] + bx) * scale;
                float oy = (acc[mi][ni][half*2+1] + by) * scale;
                if (mode == 0) {
                    float2 o; o.x = ox; o.y = oy;
                    *(float2*)(outF + (size_t)row * DM + col) = o;
                } else {
                    int b = row >> 11, s = row & 2047;
                    int h = col >> 6, dk = col & 63;
                    size_t idx = ((size_t)(b * NH + h) * SQ + s) * DKH + dk;
                    uint32_t hi, lo;
                    split2(ox, oy, hi, lo);
                    *(uint32_t*)(outHi + idx) = hi;
                    *(uint32_t*)(outLo + idx) = lo;
                }
            }
        }
    }
}

// ============================================================
// Flash attention on HMMA: Q re-ldmatrix'd per tile, 2-stage KV
// distance-1, 2 CTAs/SM, raw ex2 softmax (log2e folded into Q),
// deferred l-reduce. AO written bf16 hi/lo into g_xhi[0]/g_xlo[0].
// ============================================================
#define AQ_HI 0
#define AQ_LO 16384
#define AKV   32768
#define KVSZ  32768
#define AK_HI 0
#define AK_LO 8192
#define AV_HI 16384
#define AV_LO 24576
#define ATTN_SMEM (32768 + 2*KVSZ)   // 98304

__device__ __forceinline__ void issue_kv(uint32_t dst,
    const __nv_bfloat16* __restrict__ Kh, const __nv_bfloat16* __restrict__ Kl,
    const __nv_bfloat16* __restrict__ Vh, const __nv_bfloat16* __restrict__ Vl,
    int tid)
{
#pragma unroll
    for (int i = 0; i < 2; i++) {
        int e = tid + (i << 8);
        int row = e >> 3, un = e & 7;
        uint32_t off = ((uint32_t)row << 7) | ((uint32_t)((un ^ (row & 7)) & 7) << 4);
        size_t go = (size_t)row * DKH + un * 8;
        CP_ASYNC16(dst + AK_HI + off, (const char*)(Kh + go));
        CP_ASYNC16(dst + AK_LO + off, (const char*)(Kl + go));
        CP_ASYNC16(dst + AV_HI + off, (const char*)(Vh + go));
        CP_ASYNC16(dst + AV_LO + off, (const char*)(Vl + go));
    }
}

__global__ __launch_bounds__(256, 2)
void attn_mma()
{
    extern __shared__ __align__(1024) char smem[];
    const int tid = threadIdx.x, lane = tid & 31, wid = tid >> 5;
    const int g = lane >> 3, r = lane & 7;
    const int bq = blockIdx.x << 7, h = blockIdx.y, b = blockIdx.z;
    const size_t ho = (size_t)(b * NH + h) * SQ * DKH;
    const __nv_bfloat16* Qh = g_phi[0] + ho + (size_t)bq * DKH;
    const __nv_bfloat16* Ql = g_plo[0] + ho + (size_t)bq * DKH;
    const __nv_bfloat16* Kh = g_phi[1] + ho;
    const __nv_bfloat16* Kl = g_plo[1] + ho;
    const __nv_bfloat16* Vh = g_phi[2] + ho;
    const __nv_bfloat16* Vl = g_plo[2] + ho;
    __nv_bfloat16* aohi = g_xhi[0];
    __nv_bfloat16* aolo = g_xlo[0];
    const uint32_t sb = smem_u32(smem);

    // prologue: Q + KV0 in one group
#pragma unroll
    for (int i = 0; i < 4; i++) {
        int e = tid + (i << 8);
        int row = e >> 3, un = e & 7;
        uint32_t off = ((uint32_t)row << 7) | ((uint32_t)((un ^ (row & 7)) & 7) << 4);
        size_t go = (size_t)row * DKH + un * 8;
        CP_ASYNC16(sb + AQ_HI + off, (const char*)(Qh + go));
        CP_ASYNC16(sb + AQ_LO + off, (const char*)(Ql + go));
    }
    issue_kv(sb + AKV, Kh, Kl, Vh, Vl, tid);
    CP_COMMIT();

    float O[8][4];
#pragma unroll
    for (int nf = 0; nf < 8; nf++)
#pragma unroll
        for (int q = 0; q < 4; q++) O[nf][q] = 0.0f;
    float lsum[2] = {0.0f, 0.0f};

    const int qrow = (wid << 4) + ((g & 1) << 3) + r;
    const uint32_t qbase = (uint32_t)qrow << 7;

    const int NT = SQ / 64;  // 32
    for (int t = 0; t < NT; t++) {
        const uint32_t buf = sb + AKV + (uint32_t)(t & 1) * KVSZ;
        CP_WAIT(0);          // KV(t) (and Q on t=0) landed
        __syncthreads();     // prev tile's reads done -> other buffer reusable
        if (t + 1 < NT) {
            size_t jo = (size_t)(t + 1) * 64 * DKH;
            issue_kv(sb + AKV + (uint32_t)((t + 1) & 1) * KVSZ,
                     Kh + jo, Kl + jo, Vh + jo, Vl + jo, tid);
        }
        CP_COMMIT();

        // ---- S = Q K^T ----
        float S[8][4];
#pragma unroll
        for (int nf = 0; nf < 8; nf++)
#pragma unroll
            for (int q = 0; q < 4; q++) S[nf][q] = 0.0f;

#pragma unroll
        for (int ks = 0; ks < 4; ks++) {
            uint32_t Qfh[4], Qfl[4];
            {
                int un = (ks << 1) + (g >> 1);
                uint32_t off = qbase | ((uint32_t)((un ^ (qrow & 7)) & 7) << 4);
                ldsm4(Qfh, sb + AQ_HI + off);
                ldsm4(Qfl, sb + AQ_LO + off);
            }
            uint32_t Bh[8][2], Bl[8][2];
#pragma unroll
            for (int pp = 0; pp < 4; pp++) {
                int row = (pp << 4) + ((g >> 1) << 3) + r;
                int un = (ks << 1) + (g & 1);
                uint32_t off = ((uint32_t)row << 7) | ((uint32_t)((un ^ (row & 7)) & 7) << 4);
                uint32_t tt[4];
                ldsm4(tt, buf + AK_HI + off);
                Bh[pp*2][0] = tt[0]; Bh[pp*2][1] = tt[1];
                Bh[pp*2+1][0] = tt[2]; Bh[pp*2+1][1] = tt[3];
                ldsm4(tt, buf + AK_LO + off);
                Bl[pp*2][0] = tt[0]; Bl[pp*2][1] = tt[1];
                Bl[pp*2+1][0] = tt[2]; Bl[pp*2+1][1] = tt[3];
            }
#pragma unroll
            for (int nf = 0; nf < 8; nf++)
                mma_bf16(S[nf], Qfh, Bh[nf]);
#pragma unroll
            for (int nf = 0; nf < 8; nf++)
                mma_bf16(S[nf], Qfh, Bl[nf]);
#pragma unroll
            for (int nf = 0; nf < 8; nf++)
                mma_bf16(S[nf], Qfl, Bh[nf]);
        }

        // ---- softmax: p = 2^S (log2e pre-folded into Q) ----
#pragma unroll
        for (int hh = 0; hh < 2; hh++) {
            float sum = 0.0f;
#pragma unroll
            for (int nf = 0; nf < 8; nf++) {
                float p0 = ex2(S[nf][hh*2]);
                float p1 = ex2(S[nf][hh*2+1]);
                S[nf][hh*2] = p0; S[nf][hh*2+1] = p1;
                sum += p0 + p1;
            }
            lsum[hh] += sum;
        }

        // ---- O += P V ----
#pragma unroll
        for (int js = 0; js < 4; js++) {
            uint32_t Ph[4], Pl[4];
            split2(S[js*2][0],   S[js*2][1],   Ph[0], Pl[0]);
            split2(S[js*2][2],   S[js*2][3],   Ph[1], Pl[1]);
            split2(S[js*2+1][0], S[js*2+1][1], Ph[2], Pl[2]);
            split2(S[js*2+1][2], S[js*2+1][3], Ph[3], Pl[3]);

            uint32_t Vbh[8][2], Vbl[8][2];
#pragma unroll
            for (int pp = 0; pp < 4; pp++) {
                int row = (js << 4) + ((g & 1) << 3) + r;
                int un = (pp << 1) + (g >> 1);
                uint32_t off = ((uint32_t)row << 7) | ((uint32_t)((un ^ (row & 7)) & 7) << 4);
                uint32_t tt[4];
                ldsm4t(tt, buf + AV_HI + off);
                Vbh[pp*2][0] = tt[0]; Vbh[pp*2][1] = tt[1];
                Vbh[pp*2+1][0] = tt[2]; Vbh[pp*2+1][1] = tt[3];
                ldsm4t(tt, buf + AV_LO + off);
                Vbl[pp*2][0] = tt[0]; Vbl[pp*2][1] = tt[1];
                Vbl[pp*2+1][0] = tt[2]; Vbl[pp*2+1][1] = tt[3];
            }
#pragma unroll
            for (int nf = 0; nf < 8; nf++)
                mma_bf16(O[nf], Ph, Vbh[nf]);
#pragma unroll
            for (int nf = 0; nf < 8; nf++)
                mma_bf16(O[nf], Ph, Vbl[nf]);
#pragma unroll
            for (int nf = 0; nf < 8; nf++)
                mma_bf16(O[nf], Pl, Vbh[nf]);
        }
    }

    // ---- epilogue: deferred cross-lane l reduction, normalize, write ----
#pragma unroll
    for (int hh = 0; hh < 2; hh++) {
        lsum[hh] += __shfl_xor_sync(0xffffffffu, lsum[hh], 1);
        lsum[hh] += __shfl_xor_sync(0xffffffffu, lsum[hh], 2);
    }
    float inv0 = 1.0f / lsum[0], inv1 = 1.0f / lsum[1];
    int q0 = bq + (wid << 4) + (lane >> 2);
    size_t base0 = ((size_t)(b * SQ + q0)) * DM + h * DKH;
    size_t base1 = base0 + (size_t)8 * DM;
#pragma unroll
    for (int nf = 0; nf < 8; nf++) {
        int dk = (nf << 3) + ((lane & 3) << 1);
        uint32_t hi, lo;
        split2(O[nf][0] * inv0, O[nf][1] * inv0, hi, lo);
        *(uint32_t*)(aohi + base0 + dk) = hi;
        *(uint32_t*)(aolo + base0 + dk) = lo;
        split2(O[nf][2] * inv1, O[nf][3] * inv1, hi, lo);
        *(uint32_t*)(aohi + base1 + dk) = hi;
        *(uint32_t*)(aolo + base1 + dk) = lo;
    }
}

// ============================================================
extern "C" void kernel_launch(void* const* d_in, const int* in_sizes, int n_in,
                              void* d_out, int out_size)
{
    (void)in_sizes; (void)n_in; (void)out_size;
    const float* query = (const float*)d_in[0];
    const float* key   = (const float*)d_in[1];
    const float* value = (const float*)d_in[2];
    const float* w_q = (const float*)d_in[3];
    const float* b_q = (const float*)d_in[4];
    const float* w_k = (const float*)d_in[5];
    const float* b_k = (const float*)d_in[6];
    const float* w_v = (const float*)d_in[7];
    const float* b_v = (const float*)d_in[8];
    const float* w_o = (const float*)d_in[9];
    const float* b_o = (const float*)d_in[10];
    float* out = (float*)d_out;

    cudaFuncSetAttribute(gemm_mma, cudaFuncAttributeMaxDynamicSharedMemorySize, GEMM_SMEM);
    cudaFuncSetAttribute(attn_mma, cudaFuncAttributeMaxDynamicSharedMemorySize, ATTN_SMEM);

    const int nx4 = MTOT * DM / 4;
    dim3 cg(nx4 / 256, 7);
    dim3 gqkv(DM / GBN, MTOT / GBM, 3);    // (16, 64, 3)
    dim3 gout(DM / GBN, MTOT / GBM, 1);    // (16, 64, 1)
    dim3 agrid(SQ / 128, NH, NB);          // (16, 16, 4)

    // 1/sqrt(64) * log2(e): softmax uses raw ex2
    const float qscale = 0.125f * 1.44269504088896340736f;

    split_all<<<cg, 256>>>(query, key, value, w_q, w_k, w_v, w_o);
    gemm_mma<<<gqkv, 256, GEMM_SMEM>>>(b_q, b_k, b_v, b_o, nullptr, qscale, 1);
    attn_mma<<<agrid, 256, ATTN_SMEM>>>();
    gemm_mma<<<gout, 256, GEMM_SMEM>>>(b_q, b_k, b_v, b_o, out, qscale, 0);
}

// round 15
// speedup vs baseline: 1.5882x; 1.0368x over previous
#include <cuda_runtime.h>
#include <cuda_bf16.h>
#include <cstdint>

#define DM   1024
#define NH   16
#define DKH  64
#define NB   4
#define SQ   2048
#define MTOT (NB*SQ)   // 8192

// ---------------- scratch (device globals; no allocs allowed) ----------------
__device__ __nv_bfloat16 g_xhi[3][MTOT*DM];   // input splits (q,k,v); [0] reused for AO
__device__ __nv_bfloat16 g_xlo[3][MTOT*DM];
__device__ __nv_bfloat16 g_whi[4][DM*DM];     // wq, wk, wv, wo
__device__ __nv_bfloat16 g_wlo[4][DM*DM];
__device__ __nv_bfloat16 g_phi[3][MTOT*DM];   // projected q,k,v (head-split, hi)
__device__ __nv_bfloat16 g_plo[3][MTOT*DM];   // projected q,k,v (head-split, lo)

// ---------------- helpers ----------------
__device__ __forceinline__ uint32_t smem_u32(const void* p) {
    uint32_t a;
    asm("{ .reg .u64 t; cvta.to.shared.u64 t, %1; cvt.u32.u64 %0, t; }" : "=r"(a) : "l"(p));
    return a;
}
__device__ __forceinline__ void ldsm4(uint32_t* r, uint32_t addr) {
    asm volatile("ldmatrix.sync.aligned.m8n8.x4.shared.b16 {%0,%1,%2,%3}, [%4];"
                 : "=r"(r[0]), "=r"(r[1]), "=r"(r[2]), "=r"(r[3]) : "r"(addr));
}
__device__ __forceinline__ void ldsm4t(uint32_t* r, uint32_t addr) {
    asm volatile("ldmatrix.sync.aligned.m8n8.x4.trans.shared.b16 {%0,%1,%2,%3}, [%4];"
                 : "=r"(r[0]), "=r"(r[1]), "=r"(r[2]), "=r"(r[3]) : "r"(addr));
}
__device__ __forceinline__ void mma_bf16(float* d, const uint32_t* a, const uint32_t* b) {
    asm volatile("mma.sync.aligned.m16n8k16.row.col.f32.bf16.bf16.f32 "
                 "{%0,%1,%2,%3}, {%4,%5,%6,%7}, {%8,%9}, {%0,%1,%2,%3};"
                 : "+f"(d[0]), "+f"(d[1]), "+f"(d[2]), "+f"(d[3])
                 : "r"(a[0]), "r"(a[1]), "r"(a[2]), "r"(a[3]), "r"(b[0]), "r"(b[1]));
}
__device__ __forceinline__ float ex2(float x) {
    float y; asm("ex2.approx.ftz.f32 %0, %1;" : "=f"(y) : "f"(x)); return y;
}
#define CP_ASYNC16(dst, src) \
    asm volatile("cp.async.cg.shared.global [%0], [%1], 16;" :: "r"(dst), "l"(src))
#define CP_COMMIT() asm volatile("cp.async.commit_group;" ::: "memory")
#define CP_WAIT(N)  asm volatile("cp.async.wait_group %0;" :: "n"(N) : "memory")

__device__ __forceinline__ uint32_t bf2_bits(__nv_bfloat162 v) {
    uint32_t u; __builtin_memcpy(&u, &v, 4); return u;
}
__device__ __forceinline__ void split2(float x, float y, uint32_t& hi, uint32_t& lo) {
    __nv_bfloat162 H = __floats2bfloat162_rn(x, y);
    __nv_bfloat162 L = __floats2bfloat162_rn(x - __bfloat162float(H.x),
                                             y - __bfloat162float(H.y));
    hi = bf2_bits(H); lo = bf2_bits(L);
}

// ============================================================
// One split launch: y=0..2 inputs, y=3..6 weights
// ============================================================
__global__ __launch_bounds__(256)
void split_all(const float* __restrict__ x0, const float* __restrict__ x1,
               const float* __restrict__ x2, const float* __restrict__ w0,
               const float* __restrict__ w1, const float* __restrict__ w2,
               const float* __restrict__ w3)
{
    int i = blockIdx.x * blockDim.x + threadIdx.x;
    int s = blockIdx.y;
    const float* src;
    uint32_t *hp, *lp;
    if (s < 3) {
        src = (s == 0) ? x0 : (s == 1) ? x1 : x2;
        hp = (uint32_t*)g_xhi[s]; lp = (uint32_t*)g_xlo[s];
    } else {
        if (i >= DM * DM / 4) return;
        int w = s - 3;
        src = (w == 0) ? w0 : (w == 1) ? w1 : (w == 2) ? w2 : w3;
        hp = (uint32_t*)g_whi[w]; lp = (uint32_t*)g_wlo[w];
    }
    float4 v = ((const float4*)src)[i];
    uint32_t h0, l0, h1, l1;
    split2(v.x, v.y, h0, l0);
    split2(v.z, v.w, h1, l1);
    hp[i*2] = h0; hp[i*2+1] = h1;
    lp[i*2] = l0; lp[i*2+1] = l1;
}

// ============================================================
// HMMA GEMM: CTA tile 64x64, BK=32, 128 threads (4 warps, 32x32
// warp tile), 3-stage cp.async, 4 CTAs/SM (4 independent barrier
// domains per SM for bubble coverage).
// mode 1 (grid.z 0..2): g_xhi[z] @ g_whi[z]^T -> g_phi[z] head-split
// mode 0: g_xhi[0] @ g_whi[3]^T -> fp32 outF row-major
// ============================================================
#define GBM 64
#define GBN 64
#define GBK 32
#define NCHUNK (DM/GBK)    // 32
#define GA_OFF 0
#define GB_OFF 8192
#define BUFSZ  16384
#define GEMM_SMEM (3*BUFSZ)   // 49152

__device__ __forceinline__ void issue_chunk(uint32_t sbuf,
    const __nv_bfloat16* __restrict__ Ahi, const __nv_bfloat16* __restrict__ Alo,
    const __nv_bfloat16* __restrict__ Bhi, const __nv_bfloat16* __restrict__ Blo,
    int m0, int n0, int kb, int tid)
{
#pragma unroll
    for (int i = 0; i < 8; i++) {
        int e = tid + (i << 7);           // 0..1023
        if (e < 512) {                    // A: 64 rows x 8 units
            int row = e >> 3, un = e & 7;
            uint32_t off = ((uint32_t)row << 7) | ((uint32_t)((un ^ (row & 7)) & 7) << 4);
            const __nv_bfloat16* src = (un < 4 ? Ahi : Alo)
                                     + (size_t)(m0 + row) * DM + kb + (un & 3) * 8;
            CP_ASYNC16(sbuf + GA_OFF + off, (const char*)src);
        } else {                          // B: 64 rows x 8 units
            int eb = e - 512;
            int row = eb >> 3, un = eb & 7;
            uint32_t off = ((uint32_t)row << 7) | ((uint32_t)((un ^ (row & 7)) & 7) << 4);
            const __nv_bfloat16* src = (un < 4 ? Bhi : Blo)
                                     + (size_t)(n0 + row) * DM + kb + (un & 3) * 8;
            CP_ASYNC16(sbuf + GB_OFF + off, (const char*)src);
        }
    }
}

__global__ __launch_bounds__(128, 4)
void gemm_mma(const float* __restrict__ b0, const float* __restrict__ b1,
              const float* __restrict__ b2, const float* __restrict__ b3,
              float* __restrict__ outF, float qscale, int mode)
{
    extern __shared__ __align__(1024) char smem[];
    const int tid = threadIdx.x;
    const int lane = tid & 31, wid = tid >> 5;
    const int warp_m = (wid & 1) << 5;    // 0,32
    const int warp_n = (wid >> 1) << 5;   // 0,32
    const int m0 = blockIdx.y * GBM;
    const int n0 = blockIdx.x * GBN;
    const int z  = blockIdx.z;
    const uint32_t sbase = smem_u32(smem);

    const int za = (mode == 0) ? 0 : z;
    const int zw = (mode == 0) ? 3 : z;
    const __nv_bfloat16* Ahi = g_xhi[za];
    const __nv_bfloat16* Alo = g_xlo[za];
    const __nv_bfloat16* Bhi = g_whi[zw];
    const __nv_bfloat16* Blo = g_wlo[zw];
    const float* bias = (mode == 0) ? b3 : (z == 0 ? b0 : (z == 1 ? b1 : b2));
    const float scale = (mode == 1 && z == 0) ? qscale : 1.0f;

    float acc[2][4][4];
#pragma unroll
    for (int mi = 0; mi < 2; mi++)
#pragma unroll
        for (int ni = 0; ni < 4; ni++)
#pragma unroll
            for (int q = 0; q < 4; q++) acc[mi][ni][q] = 0.0f;

    const int g = lane >> 3, r = lane & 7;

    issue_chunk(sbase, Ahi, Alo, Bhi, Blo, m0, n0, 0, tid);
    CP_COMMIT();
    issue_chunk(sbase + BUFSZ, Ahi, Alo, Bhi, Blo, m0, n0, GBK, tid);
    CP_COMMIT();

    for (int kc = 0; kc < NCHUNK; kc++) {
        const uint32_t buf = sbase + (uint32_t)(kc % 3) * BUFSZ;
        CP_WAIT(1);
        __syncthreads();
        if (kc + 2 < NCHUNK)
            issue_chunk(sbase + (uint32_t)((kc + 2) % 3) * BUFSZ,
                        Ahi, Alo, Bhi, Blo, m0, n0, (kc + 2) * GBK, tid);
        CP_COMMIT();

#pragma unroll
        for (int ks = 0; ks < 2; ks++) {
            uint32_t Ah[2][4], Al[2][4], Bh[4][2], Bl[4][2];
            {
                int kun = (ks << 1) + (g >> 1);
#pragma unroll
                for (int mi = 0; mi < 2; mi++) {
                    int rowl = warp_m + ((g & 1) << 3) + r + (mi << 4);
                    uint32_t base = (uint32_t)rowl << 7;
                    ldsm4(Ah[mi], buf + GA_OFF + base + ((uint32_t)((kun ^ (rowl & 7)) & 7) << 4));
                    ldsm4(Al[mi], buf + GA_OFF + base + ((uint32_t)(((kun + 4) ^ (rowl & 7)) & 7) << 4));
                }
            }
            {
                int kun = (ks << 1) + (g & 1);
#pragma unroll
                for (int nh = 0; nh < 2; nh++) {
                    int rowl = warp_n + ((g >> 1) << 3) + r + (nh << 4);
                    uint32_t base = (uint32_t)rowl << 7;
                    uint32_t t[4];
                    ldsm4(t, buf + GB_OFF + base + ((uint32_t)((kun ^ (rowl & 7)) & 7) << 4));
                    Bh[nh*2][0] = t[0]; Bh[nh*2][1] = t[1];
                    Bh[nh*2+1][0] = t[2]; Bh[nh*2+1][1] = t[3];
                    ldsm4(t, buf + GB_OFF + base + ((uint32_t)(((kun + 4) ^ (rowl & 7)) & 7) << 4));
                    Bl[nh*2][0] = t[0]; Bl[nh*2][1] = t[1];
                    Bl[nh*2+1][0] = t[2]; Bl[nh*2+1][1] = t[3];
                }
            }
#pragma unroll
            for (int mi = 0; mi < 2; mi++)
#pragma unroll
                for (int ni = 0; ni < 4; ni++)
                    mma_bf16(acc[mi][ni], Ah[mi], Bh[ni]);
#pragma unroll
            for (int mi = 0; mi < 2; mi++)
#pragma unroll
                for (int ni = 0; ni < 4; ni++)
                    mma_bf16(acc[mi][ni], Ah[mi], Bl[ni]);
#pragma unroll
            for (int mi = 0; mi < 2; mi++)
#pragma unroll
                for (int ni = 0; ni < 4; ni++)
                    mma_bf16(acc[mi][ni], Al[mi], Bh[ni]);
        }
    }

    __nv_bfloat16* outHi = g_phi[z];
    __nv_bfloat16* outLo = g_plo[z];
    const int er = lane >> 2, ec = (lane & 3) << 1;
#pragma unroll
    for (int mi = 0; mi < 2; mi++) {
#pragma unroll
        for (int ni = 0; ni < 4; ni++) {
            int col = n0 + warp_n + (ni << 3) + ec;
            float bx = __ldg(bias + col), by = __ldg(bias + col + 1);
#pragma unroll
            for (int half = 0; half < 2; half++) {
                int row = m0 + warp_m + (mi << 4) + er + (half << 3);
                float ox = (acc[mi][ni][half*2+0] + bx) * scale;
                float oy = (acc[mi][ni][half*2+1] + by) * scale;
                if (mode == 0) {
                    float2 o; o.x = ox; o.y = oy;
                    *(float2*)(outF + (size_t)row * DM + col) = o;
                } else {
                    int b = row >> 11, s = row & 2047;
                    int h = col >> 6, dk = col & 63;
                    size_t idx = ((size_t)(b * NH + h) * SQ + s) * DKH + dk;
                    uint32_t hi, lo;
                    split2(ox, oy, hi, lo);
                    *(uint32_t*)(outHi + idx) = hi;
                    *(uint32_t*)(outLo + idx) = lo;
                }
            }
        }
    }
}

// ============================================================
// Flash attention on HMMA (unchanged R14/R9-best): Q re-ldmatrix'd
// per tile, 2-stage KV distance-1, 2 CTAs/SM, raw ex2 softmax,
// deferred l-reduce. AO written bf16 hi/lo into g_xhi[0]/g_xlo[0].
// ============================================================
#define AQ_HI 0
#define AQ_LO 16384
#define AKV   32768
#define KVSZ  32768
#define AK_HI 0
#define AK_LO 8192
#define AV_HI 16384
#define AV_LO 24576
#define ATTN_SMEM (32768 + 2*KVSZ)   // 98304

__device__ __forceinline__ void issue_kv(uint32_t dst,
    const __nv_bfloat16* __restrict__ Kh, const __nv_bfloat16* __restrict__ Kl,
    const __nv_bfloat16* __restrict__ Vh, const __nv_bfloat16* __restrict__ Vl,
    int tid)
{
#pragma unroll
    for (int i = 0; i < 2; i++) {
        int e = tid + (i << 8);
        int row = e >> 3, un = e & 7;
        uint32_t off = ((uint32_t)row << 7) | ((uint32_t)((un ^ (row & 7)) & 7) << 4);
        size_t go = (size_t)row * DKH + un * 8;
        CP_ASYNC16(dst + AK_HI + off, (const char*)(Kh + go));
        CP_ASYNC16(dst + AK_LO + off, (const char*)(Kl + go));
        CP_ASYNC16(dst + AV_HI + off, (const char*)(Vh + go));
        CP_ASYNC16(dst + AV_LO + off, (const char*)(Vl + go));
    }
}

__global__ __launch_bounds__(256, 2)
void attn_mma()
{
    extern __shared__ __align__(1024) char smem[];
    const int tid = threadIdx.x, lane = tid & 31, wid = tid >> 5;
    const int g = lane >> 3, r = lane & 7;
    const int bq = blockIdx.x << 7, h = blockIdx.y, b = blockIdx.z;
    const size_t ho = (size_t)(b * NH + h) * SQ * DKH;
    const __nv_bfloat16* Qh = g_phi[0] + ho + (size_t)bq * DKH;
    const __nv_bfloat16* Ql = g_plo[0] + ho + (size_t)bq * DKH;
    const __nv_bfloat16* Kh = g_phi[1] + ho;
    const __nv_bfloat16* Kl = g_plo[1] + ho;
    const __nv_bfloat16* Vh = g_phi[2] + ho;
    const __nv_bfloat16* Vl = g_plo[2] + ho;
    __nv_bfloat16* aohi = g_xhi[0];
    __nv_bfloat16* aolo = g_xlo[0];
    const uint32_t sb = smem_u32(smem);

#pragma unroll
    for (int i = 0; i < 4; i++) {
        int e = tid + (i << 8);
        int row = e >> 3, un = e & 7;
        uint32_t off = ((uint32_t)row << 7) | ((uint32_t)((un ^ (row & 7)) & 7) << 4);
        size_t go = (size_t)row * DKH + un * 8;
        CP_ASYNC16(sb + AQ_HI + off, (const char*)(Qh + go));
        CP_ASYNC16(sb + AQ_LO + off, (const char*)(Ql + go));
    }
    issue_kv(sb + AKV, Kh, Kl, Vh, Vl, tid);
    CP_COMMIT();

    float O[8][4];
#pragma unroll
    for (int nf = 0; nf < 8; nf++)
#pragma unroll
        for (int q = 0; q < 4; q++) O[nf][q] = 0.0f;
    float lsum[2] = {0.0f, 0.0f};

    const int qrow = (wid << 4) + ((g & 1) << 3) + r;
    const uint32_t qbase = (uint32_t)qrow << 7;

    const int NT = SQ / 64;  // 32
    for (int t = 0; t < NT; t++) {
        const uint32_t buf = sb + AKV + (uint32_t)(t & 1) * KVSZ;
        CP_WAIT(0);
        __syncthreads();
        if (t + 1 < NT) {
            size_t jo = (size_t)(t + 1) * 64 * DKH;
            issue_kv(sb + AKV + (uint32_t)((t + 1) & 1) * KVSZ,
                     Kh + jo, Kl + jo, Vh + jo, Vl + jo, tid);
        }
        CP_COMMIT();

        // ---- S = Q K^T ----
        float S[8][4];
#pragma unroll
        for (int nf = 0; nf < 8; nf++)
#pragma unroll
            for (int q = 0; q < 4; q++) S[nf][q] = 0.0f;

#pragma unroll
        for (int ks = 0; ks < 4; ks++) {
            uint32_t Qfh[4], Qfl[4];
            {
                int un = (ks << 1) + (g >> 1);
                uint32_t off = qbase | ((uint32_t)((un ^ (qrow & 7)) & 7) << 4);
                ldsm4(Qfh, sb + AQ_HI + off);
                ldsm4(Qfl, sb + AQ_LO + off);
            }
            uint32_t Bh[8][2], Bl[8][2];
#pragma unroll
            for (int pp = 0; pp < 4; pp++) {
                int row = (pp << 4) + ((g >> 1) << 3) + r;
                int un = (ks << 1) + (g & 1);
                uint32_t off = ((uint32_t)row << 7) | ((uint32_t)((un ^ (row & 7)) & 7) << 4);
                uint32_t tt[4];
                ldsm4(tt, buf + AK_HI + off);
                Bh[pp*2][0] = tt[0]; Bh[pp*2][1] = tt[1];
                Bh[pp*2+1][0] = tt[2]; Bh[pp*2+1][1] = tt[3];
                ldsm4(tt, buf + AK_LO + off);
                Bl[pp*2][0] = tt[0]; Bl[pp*2][1] = tt[1];
                Bl[pp*2+1][0] = tt[2]; Bl[pp*2+1][1] = tt[3];
            }
#pragma unroll
            for (int nf = 0; nf < 8; nf++)
                mma_bf16(S[nf], Qfh, Bh[nf]);
#pragma unroll
            for (int nf = 0; nf < 8; nf++)
                mma_bf16(S[nf], Qfh, Bl[nf]);
#pragma unroll
            for (int nf = 0; nf < 8; nf++)
                mma_bf16(S[nf], Qfl, Bh[nf]);
        }

        // ---- softmax: p = 2^S (log2e pre-folded into Q) ----
#pragma unroll
        for (int hh = 0; hh < 2; hh++) {
            float sum = 0.0f;
#pragma unroll
            for (int nf = 0; nf < 8; nf++) {
                float p0 = ex2(S[nf][hh*2]);
                float p1 = ex2(S[nf][hh*2+1]);
                S[nf][hh*2] = p0; S[nf][hh*2+1] = p1;
                sum += p0 + p1;
            }
            lsum[hh] += sum;
        }

        // ---- O += P V ----
#pragma unroll
        for (int js = 0; js < 4; js++) {
            uint32_t Ph[4], Pl[4];
            split2(S[js*2][0],   S[js*2][1],   Ph[0], Pl[0]);
            split2(S[js*2][2],   S[js*2][3],   Ph[1], Pl[1]);
            split2(S[js*2+1][0], S[js*2+1][1], Ph[2], Pl[2]);
            split2(S[js*2+1][2], S[js*2+1][3], Ph[3], Pl[3]);

            uint32_t Vbh[8][2], Vbl[8][2];
#pragma unroll
            for (int pp = 0; pp < 4; pp++) {
                int row = (js << 4) + ((g & 1) << 3) + r;
                int un = (pp << 1) + (g >> 1);
                uint32_t off = ((uint32_t)row << 7) | ((uint32_t)((un ^ (row & 7)) & 7) << 4);
                uint32_t tt[4];
                ldsm4t(tt, buf + AV_HI + off);
                Vbh[pp*2][0] = tt[0]; Vbh[pp*2][1] = tt[1];
                Vbh[pp*2+1][0] = tt[2]; Vbh[pp*2+1][1] = tt[3];
                ldsm4t(tt, buf + AV_LO + off);
                Vbl[pp*2][0] = tt[0]; Vbl[pp*2][1] = tt[1];
                Vbl[pp*2+1][0] = tt[2]; Vbl[pp*2+1][1] = tt[3];
            }
#pragma unroll
            for (int nf = 0; nf < 8; nf++)
                mma_bf16(O[nf], Ph, Vbh[nf]);
#pragma unroll
            for (int nf = 0; nf < 8; nf++)
                mma_bf16(O[nf], Ph, Vbl[nf]);
#pragma unroll
            for (int nf = 0; nf < 8; nf++)
                mma_bf16(O[nf], Pl, Vbh[nf]);
        }
    }

    // ---- epilogue ----
#pragma unroll
    for (int hh = 0; hh < 2; hh++) {
        lsum[hh] += __shfl_xor_sync(0xffffffffu, lsum[hh], 1);
        lsum[hh] += __shfl_xor_sync(0xffffffffu, lsum[hh], 2);
    }
    float inv0 = 1.0f / lsum[0], inv1 = 1.0f / lsum[1];
    int q0 = bq + (wid << 4) + (lane >> 2);
    size_t base0 = ((size_t)(b * SQ + q0)) * DM + h * DKH;
    size_t base1 = base0 + (size_t)8 * DM;
#pragma unroll
    for (int nf = 0; nf < 8; nf++) {
        int dk = (nf << 3) + ((lane & 3) << 1);
        uint32_t hi, lo;
        split2(O[nf][0] * inv0, O[nf][1] * inv0, hi, lo);
        *(uint32_t*)(aohi + base0 + dk) = hi;
        *(uint32_t*)(aolo + base0 + dk) = lo;
        split2(O[nf][2] * inv1, O[nf][3] * inv1, hi, lo);
        *(uint32_t*)(aohi + base1 + dk) = hi;
        *(uint32_t*)(aolo + base1 + dk) = lo;
    }
}

// ============================================================
extern "C" void kernel_launch(void* const* d_in, const int* in_sizes, int n_in,
                              void* d_out, int out_size)
{
    (void)in_sizes; (void)n_in; (void)out_size;
    const float* query = (const float*)d_in[0];
    const float* key   = (const float*)d_in[1];
    const float* value = (const float*)d_in[2];
    const float* w_q = (const float*)d_in[3];
    const float* b_q = (const float*)d_in[4];
    const float* w_k = (const float*)d_in[5];
    const float* b_k = (const float*)d_in[6];
    const float* w_v = (const float*)d_in[7];
    const float* b_v = (const float*)d_in[8];
    const float* w_o = (const float*)d_in[9];
    const float* b_o = (const float*)d_in[10];
    float* out = (float*)d_out;

    cudaFuncSetAttribute(gemm_mma, cudaFuncAttributeMaxDynamicSharedMemorySize, GEMM_SMEM);
    cudaFuncSetAttribute(attn_mma, cudaFuncAttributeMaxDynamicSharedMemorySize, ATTN_SMEM);

    const int nx4 = MTOT * DM / 4;
    dim3 cg(nx4 / 256, 7);
    dim3 gqkv(DM / GBN, MTOT / GBM, 3);    // (16, 128, 3)
    dim3 gout(DM / GBN, MTOT / GBM, 1);    // (16, 128, 1)
    dim3 agrid(SQ / 128, NH, NB);          // (16, 16, 4)

    // 1/sqrt(64) * log2(e): softmax uses raw ex2
    const float qscale = 0.125f * 1.44269504088896340736f;

    split_all<<<cg, 256>>>(query, key, value, w_q, w_k, w_v, w_o);
    gemm_mma<<<gqkv, 128, GEMM_SMEM>>>(b_q, b_k, b_v, b_o, nullptr, qscale, 1);
    attn_mma<<<agrid, 256, ATTN_SMEM>>>();
    gemm_mma<<<gout, 128, GEMM_SMEM>>>(b_q, b_k, b_v, b_o, out, qscale, 0);
}